// round 1
// baseline (speedup 1.0000x reference)
#include <cuda_runtime.h>
#include <math.h>

#define BB 16
#define NPIX 245760          // 384*640
#define N2  491520           // 2*NPIX
#define NQTOT 96             // 64 gt queries + 32 r queries

// ---------------- scratch (static device memory; no runtime allocs) ----------------
__device__ double g_sums[BB][5];                    // a00,a01,a11,b0,b1
__device__ int    g_nmask[BB];
__device__ int    g_cnt[BB];                        // static-pixel count
__device__ float  g_sf[BB], g_tf[BB], g_rr[BB], g_th[BB], g_scale[BB];
__device__ int    g_k[BB];
__device__ unsigned int g_q_rank[NQTOT];            // remaining rank per query
__device__ unsigned int g_q_prefix[NQTOT];          // resolved high bits / final key
__device__ unsigned int g_hist[NQTOT][2048];
__device__ float        g_hub_sum[32];
__device__ unsigned int g_less[32];
__device__ unsigned int g_gt_keys[(size_t)BB * N2];   // 31.5 MB
__device__ unsigned int g_rd_keys[(size_t)BB * NPIX]; // 15.7 MB
__device__ unsigned int g_ra_keys[(size_t)BB * NPIX]; // 15.7 MB

// ---------------- helpers ----------------
__device__ __forceinline__ unsigned int fkey(float x) {
    unsigned int u = __float_as_uint(x);
    return (u & 0x80000000u) ? ~u : (u | 0x80000000u);
}
__device__ __forceinline__ float kinv(unsigned int k) {
    unsigned int u = (k & 0x80000000u) ? (k & 0x7fffffffu) : ~k;
    return __uint_as_float(u);
}
__device__ __forceinline__ float hubf(float v) {
    // reference: v<=DELTA ? 0.5*v^2/DELTA : v - 0.5*DELTA, DELTA=0.03
    return (v <= 0.03f) ? (0.5f * (v * v)) / 0.03f : (v - 0.015f);
}

// ---------------- kernels ----------------
__global__ void k_zero() {
    int i = blockIdx.x * blockDim.x + threadIdx.x;
    int stride = gridDim.x * blockDim.x;
    for (int x = i; x < NQTOT * 2048; x += stride) ((unsigned int*)g_hist)[x] = 0u;
    if (i < BB) {
        for (int j = 0; j < 5; j++) g_sums[i][j] = 0.0;
        g_cnt[i] = 0;
        g_nmask[i] = 0;
    }
}

// Pass 1: masked moment sums + gt key materialization
__global__ void k_stats(const float* __restrict__ pred, const float* __restrict__ gt,
                        const float* __restrict__ mask) {
    int b = blockIdx.y;
    const float4* p4 = (const float4*)(pred + (size_t)b * N2);
    const float4* g4 = (const float4*)(gt   + (size_t)b * N2);
    const float4* m4 = (const float4*)(mask + (size_t)b * N2);
    uint4* k4 = (uint4*)(g_gt_keys + (size_t)b * N2);
    float a00 = 0.f, a01 = 0.f, a11 = 0.f, bb0 = 0.f, bb1 = 0.f;
    int n4 = N2 / 4;
    for (int i = blockIdx.x * blockDim.x + threadIdx.x; i < n4; i += gridDim.x * blockDim.x) {
        float4 p = p4[i], g = g4[i], m = m4[i];
        uint4 kk;
#define DO(c) { if (m.c > 0.5f) { a00 += p.c * p.c; a01 += p.c; a11 += 1.f; \
                                  bb0 += p.c * g.c; bb1 += g.c; kk.c = fkey(g.c); } \
                else kk.c = 0xffffffffu; }
        DO(x) DO(y) DO(z) DO(w)
#undef DO
        k4[i] = kk;
    }
    double d0 = a00, d1 = a01, d2 = a11, d3 = bb0, d4 = bb1;
    for (int off = 16; off > 0; off >>= 1) {
        d0 += __shfl_down_sync(0xffffffffu, d0, off);
        d1 += __shfl_down_sync(0xffffffffu, d1, off);
        d2 += __shfl_down_sync(0xffffffffu, d2, off);
        d3 += __shfl_down_sync(0xffffffffu, d3, off);
        d4 += __shfl_down_sync(0xffffffffu, d4, off);
    }
    __shared__ double sh[8][5];
    int lane = threadIdx.x & 31, w = threadIdx.x >> 5;
    if (lane == 0) { sh[w][0] = d0; sh[w][1] = d1; sh[w][2] = d2; sh[w][3] = d3; sh[w][4] = d4; }
    __syncthreads();
    if (threadIdx.x == 0) {
        double s0 = 0, s1 = 0, s2 = 0, s3 = 0, s4 = 0;
        for (int ww = 0; ww < 8; ww++) { s0 += sh[ww][0]; s1 += sh[ww][1]; s2 += sh[ww][2]; s3 += sh[ww][3]; s4 += sh[ww][4]; }
        atomicAdd(&g_sums[b][0], s0); atomicAdd(&g_sums[b][1], s1);
        atomicAdd(&g_sums[b][2], s2); atomicAdd(&g_sums[b][3], s3);
        atomicAdd(&g_sums[b][4], s4);
    }
}

__global__ void k_solve1() {
    int b = threadIdx.x;
    if (b >= BB) return;
    double a00 = g_sums[b][0], a01 = g_sums[b][1], a11 = g_sums[b][2];
    double bb0 = g_sums[b][3], bb1 = g_sums[b][4];
    double det = a00 * a11 - a01 * a01;
    float s = 0.f, t = 0.f;
    if (det != 0.0) {
        double id = 1.0 / (det + 1e-6);
        s = (float)((a11 * bb0 - a01 * bb1) * id);
        t = (float)((-a01 * bb0 + a00 * bb1) * id);
    }
    g_sf[b] = s; g_tf[b] = t;
    int n = (int)(a11 + 0.5);
    g_nmask[b] = n;
    int nm1 = (n > 1) ? (n - 1) : 0;
    float pos05 = 0.05f * (float)nm1;
    float pos95 = 0.95f * (float)nm1;
    g_q_rank[b * 4 + 0] = (unsigned)floorf(pos05);
    g_q_rank[b * 4 + 1] = (unsigned)ceilf(pos05);
    g_q_rank[b * 4 + 2] = (unsigned)floorf(pos95);
    g_q_rank[b * 4 + 3] = (unsigned)ceilf(pos95);
    for (int j = 0; j < 4; j++) g_q_prefix[b * 4 + j] = 0u;
}

__global__ void k_hist_gt0() {
    __shared__ unsigned int h[2048];
    int b = blockIdx.y;
    for (int i = threadIdx.x; i < 2048; i += blockDim.x) h[i] = 0u;
    __syncthreads();
    const uint4* k4 = (const uint4*)(g_gt_keys + (size_t)b * N2);
    int n4 = N2 / 4;
    for (int i = blockIdx.x * blockDim.x + threadIdx.x; i < n4; i += gridDim.x * blockDim.x) {
        uint4 k = k4[i];
        atomicAdd(&h[k.x >> 21], 1u); atomicAdd(&h[k.y >> 21], 1u);
        atomicAdd(&h[k.z >> 21], 1u); atomicAdd(&h[k.w >> 21], 1u);
    }
    __syncthreads();
    unsigned int* gh = g_hist[b * 4];
    for (int i = threadIdx.x; i < 2048; i += blockDim.x) {
        unsigned v = h[i];
        if (v) atomicAdd(&gh[i], v);
    }
}

__global__ void k_hist_gt(int level) {  // level 1 or 2
    __shared__ unsigned int h[4][2048];
    int b = blockIdx.y;
    for (int i = threadIdx.x; i < 4 * 2048; i += blockDim.x) ((unsigned int*)h)[i] = 0u;
    __syncthreads();
    unsigned pref0 = g_q_prefix[b * 4 + 0], pref1 = g_q_prefix[b * 4 + 1];
    unsigned pref2 = g_q_prefix[b * 4 + 2], pref3 = g_q_prefix[b * 4 + 3];
    int hishift = (level == 1) ? 21 : 10;
    int shift   = (level == 1) ? 10 : 0;
    unsigned bmask = (level == 1) ? 2047u : 1023u;
    const uint4* k4 = (const uint4*)(g_gt_keys + (size_t)b * N2);
    int n4 = N2 / 4;
    for (int i = blockIdx.x * blockDim.x + threadIdx.x; i < n4; i += gridDim.x * blockDim.x) {
        uint4 kk = k4[i];
        unsigned a[4] = {kk.x, kk.y, kk.z, kk.w};
#pragma unroll
        for (int e = 0; e < 4; e++) {
            unsigned key = a[e];
            unsigned hi = key >> hishift;
            unsigned bin = (key >> shift) & bmask;
            if (hi == pref0) atomicAdd(&h[0][bin], 1u);
            if (hi == pref1) atomicAdd(&h[1][bin], 1u);
            if (hi == pref2) atomicAdd(&h[2][bin], 1u);
            if (hi == pref3) atomicAdd(&h[3][bin], 1u);
        }
    }
    __syncthreads();
    for (int j = 0; j < 4; j++)
        for (int i = threadIdx.x; i < 2048; i += blockDim.x) {
            unsigned v = h[j][i];
            if (v) atomicAdd(&g_hist[b * 4 + j][i], v);
        }
}

// One block; qcount <= blockDim. share=4 -> queries in groups of 4 read group-leader hist.
__global__ void k_resolve(int qlo, int qcount, int nbins, int share) {
    int idx = threadIdx.x;
    if (idx < qcount) {
        int q = qlo + idx;
        int hq = qlo + (idx / share) * share;
        unsigned rank = g_q_rank[q];
        const unsigned int* hist = g_hist[hq];
        unsigned cum = 0, sel = 0, rem = 0;
        bool found = false;
        for (int bin = 0; bin < nbins; bin++) {
            unsigned c = hist[bin];
            if (!found) {
                if (cum + c > rank) { sel = (unsigned)bin; rem = rank - cum; found = true; }
                else cum += c;
            }
        }
        g_q_rank[q] = rem;
        g_q_prefix[q] = g_q_prefix[q] * (unsigned)nbins + sel;
    }
    __syncthreads();
    if (idx < qcount && (idx % share) == 0) {
        unsigned int* hist = g_hist[qlo + idx];
        for (int bin = 0; bin < nbins; bin++) hist[bin] = 0u;
    }
}

__global__ void k_rr() {
    int b = threadIdx.x;
    if (b >= BB) return;
    int n = g_nmask[b];
    float rr = 1.0f;
    if (n > 0) {
        float v0 = kinv(g_q_prefix[b * 4 + 0]);
        float v1 = kinv(g_q_prefix[b * 4 + 1]);
        float v2 = kinv(g_q_prefix[b * 4 + 2]);
        float v3 = kinv(g_q_prefix[b * 4 + 3]);
        int nm1 = (n > 1) ? (n - 1) : 0;
        float pos05 = 0.05f * (float)nm1, pos95 = 0.95f * (float)nm1;
        float lo = v0 + (v1 - v0) * (pos05 - floorf(pos05));
        float hi = v2 + (v3 - v2) * (pos95 - floorf(pos95));
        bool valid = isfinite(lo) && isfinite(hi) && (hi - lo > 0.f) &&
                     (fabsf(lo) < 1e30f) && (fabsf(hi) < 1e30f);
        rr = valid ? fmaxf(hi - lo, 1e-6f) : 1.0f;
    }
    g_rr[b] = rr;
    g_scale[b] = fmaxf(rr, 1e-6f);
    g_th[b] = 0.01f * rr;
}

// curr_grad output + compaction of static residual keys
__global__ void k_compact(const float* __restrict__ pred, const float* __restrict__ gt,
                          const float* __restrict__ mask, const float* __restrict__ prev,
                          float* __restrict__ out) {
    int b = blockIdx.y;
    float s = g_sf[b], t = g_tf[b], th = g_th[b], sc = g_scale[b];
    const float4* p0 = (const float4*)(pred + (size_t)b * N2);
    const float4* p1 = (const float4*)(pred + (size_t)b * N2 + NPIX);
    const float4* g0 = (const float4*)(gt   + (size_t)b * N2);
    const float4* g1 = (const float4*)(gt   + (size_t)b * N2 + NPIX);
    const float4* m0 = (const float4*)(mask + (size_t)b * N2);
    const float4* m1 = (const float4*)(mask + (size_t)b * N2 + NPIX);
    const float4* pv = (const float4*)(prev + (size_t)b * NPIX);
    float4* o4 = (float4*)(out + 4 + (size_t)b * NPIX);
    int n4 = NPIX / 4;
    for (int i = blockIdx.x * blockDim.x + threadIdx.x; i < n4; i += gridDim.x * blockDim.x) {
        float4 P0 = p0[i], P1 = p1[i], G0 = g0[i], G1 = g1[i], M0 = m0[i], M1 = m1[i], PV = pv[i];
        float4 DP;
#define DO(c) { float A0 = fmaf(s, P0.c, t); float A1 = fmaf(s, P1.c, t); \
                float dp = A1 - A0; DP.c = dp; \
                float dg = G1.c - G0.c; \
                if (M0.c > 0.5f && M1.c > 0.5f && fabsf(dg) < th) { \
                    int pos = atomicAdd(&g_cnt[b], 1); \
                    g_rd_keys[(size_t)b * NPIX + pos] = fkey(fabsf(dp - dg) / sc); \
                    g_ra_keys[(size_t)b * NPIX + pos] = fkey(fabsf(dp - PV.c) / sc); } }
        DO(x) DO(y) DO(z) DO(w)
#undef DO
        o4[i] = DP;
    }
}

__global__ void k_solve2() {
    int b = threadIdx.x;
    if (b >= BB) return;
    int n = g_cnt[b];
    int k = (int)floorf(0.6f * (float)n);   // (1.0-TRIM) as f32, mirrors reference
    g_k[b] = k;
    unsigned r = (k > 0) ? (unsigned)(k - 1) : 0u;
    g_q_rank[64 + b * 2 + 0] = r;  g_q_rank[64 + b * 2 + 1] = r;
    g_q_prefix[64 + b * 2 + 0] = 0u; g_q_prefix[64 + b * 2 + 1] = 0u;
}

__global__ void k_hist_r(int level) {
    __shared__ unsigned int h[2][2048];
    int b = blockIdx.y;
    for (int i = threadIdx.x; i < 4096; i += blockDim.x) ((unsigned int*)h)[i] = 0u;
    __syncthreads();
    int cnt = g_cnt[b];
    unsigned pref0 = g_q_prefix[64 + b * 2 + 0], pref1 = g_q_prefix[64 + b * 2 + 1];
    int hishift = (level == 1) ? 21 : 10;
    int shift   = (level == 1) ? 10 : 0;
    unsigned bmask = (level == 1) ? 2047u : 1023u;
    for (int i = threadIdx.x; i < cnt; i += blockDim.x) {
        unsigned kd = g_rd_keys[(size_t)b * NPIX + i];
        unsigned ka = g_ra_keys[(size_t)b * NPIX + i];
        if (level == 0) {
            atomicAdd(&h[0][kd >> 21], 1u);
            atomicAdd(&h[1][ka >> 21], 1u);
        } else {
            if ((kd >> hishift) == pref0) atomicAdd(&h[0][(kd >> shift) & bmask], 1u);
            if ((ka >> hishift) == pref1) atomicAdd(&h[1][(ka >> shift) & bmask], 1u);
        }
    }
    __syncthreads();
    // single block per batch -> plain stores (hist was zero before)
    for (int i = threadIdx.x; i < 2048; i += blockDim.x) {
        g_hist[64 + b * 2 + 0][i] = h[0][i];
        g_hist[64 + b * 2 + 1][i] = h[1][i];
    }
}

__global__ void k_hubersum() {
    int b = blockIdx.y, j = blockIdx.x;
    unsigned tkey = g_q_prefix[64 + b * 2 + j];
    const unsigned int* keys = (j == 0 ? g_rd_keys : g_ra_keys) + (size_t)b * NPIX;
    int cnt = g_cnt[b];
    float sum = 0.f;
    unsigned less = 0;
    for (int i = threadIdx.x; i < cnt; i += blockDim.x) {
        unsigned key = keys[i];
        if (key < tkey) { sum += hubf(kinv(key)); less++; }
    }
    for (int off = 16; off > 0; off >>= 1) {
        sum  += __shfl_down_sync(0xffffffffu, sum, off);
        less += __shfl_down_sync(0xffffffffu, less, off);
    }
    __shared__ float ss[8];
    __shared__ unsigned sl[8];
    int lane = threadIdx.x & 31, w = threadIdx.x >> 5;
    if (lane == 0) { ss[w] = sum; sl[w] = less; }
    __syncthreads();
    if (threadIdx.x == 0) {
        float S = 0.f; unsigned L = 0;
        for (int ww = 0; ww < 8; ww++) { S += ss[ww]; L += sl[ww]; }
        g_hub_sum[b * 2 + j] = S;
        g_less[b * 2 + j] = L;
    }
}

__global__ void k_final(float* __restrict__ out) {
    __shared__ float ld[BB], la[BB], rs[BB];
    int b = threadIdx.x;
    if (b < BB) {
        int k = g_k[b];
        float lj[2];
        for (int j = 0; j < 2; j++) {
            if (k > 0) {
                float tv = kinv(g_q_prefix[64 + b * 2 + j]);
                float ht = hubf(tv);
                float S = g_hub_sum[b * 2 + j] + (float)(k - (int)g_less[b * 2 + j]) * ht;
                lj[j] = S / (float)k;
            } else lj[j] = 0.f;
        }
        ld[b] = lj[0]; la[b] = lj[1]; rs[b] = g_rr[b];
    }
    __syncthreads();
    if (threadIdx.x == 0) {
        float sld = 0.f, sla = 0.f, srr = 0.f;
        for (int i = 0; i < BB; i++) { sld += ld[i]; sla += la[i]; srr += rs[i]; }
        float loss_data = sld / (float)BB;
        float loss_acc  = sla / (float)BB;
        float rrm       = srr / (float)BB;
        out[0] = loss_data + 0.2f * loss_acc;
        out[1] = loss_data;
        out[2] = loss_acc;
        out[3] = rrm;
    }
}

extern "C" void kernel_launch(void* const* d_in, const int* in_sizes, int n_in,
                              void* d_out, int out_size) {
    const float* pred = (const float*)d_in[0];
    const float* gt   = (const float*)d_in[1];
    const float* mask = (const float*)d_in[2];
    const float* prev = (const float*)d_in[3];
    float* out = (float*)d_out;
    dim3 big(60, BB);

    k_zero<<<96, 256>>>();
    k_stats<<<big, 256>>>(pred, gt, mask);
    k_solve1<<<1, 32>>>();

    // gt quantile radix select (3 levels: 11/11/10 bits)
    k_hist_gt0<<<big, 256>>>();
    k_resolve<<<1, 64>>>(0, 64, 2048, 4);
    k_hist_gt<<<big, 256>>>(1);
    k_resolve<<<1, 64>>>(0, 64, 2048, 1);
    k_hist_gt<<<big, 256>>>(2);
    k_resolve<<<1, 64>>>(0, 64, 1024, 1);
    k_rr<<<1, 16>>>();

    // residuals + curr_grad output + static compaction
    k_compact<<<big, 256>>>(pred, gt, mask, prev, out);
    k_solve2<<<1, 16>>>();

    // trimmed-huber threshold radix select on compacted arrays
    for (int L = 0; L < 3; L++) {
        k_hist_r<<<dim3(1, BB), 256>>>(L);
        k_resolve<<<1, 32>>>(64, 32, (L == 2) ? 1024 : 2048, 1);
    }
    k_hubersum<<<dim3(2, BB), 256>>>();
    k_final<<<1, 32>>>(out);
}

// round 2
// speedup vs baseline: 7.6437x; 7.6437x over previous
#include <cuda_runtime.h>
#include <math.h>

#define BB 16
#define NPIX 245760          // 384*640
#define N2  491520           // 2*NPIX

// ---------------- scratch (static device memory; no runtime allocs) ----------------
__device__ double g_sums[BB][5];                    // a00,a01,a11,b0,b1
__device__ int    g_nmask[BB];
__device__ int    g_cnt[BB];                        // static-pixel count
__device__ float  g_sf[BB], g_tf[BB], g_rr[BB], g_th[BB], g_scale[BB];
__device__ unsigned int g_q_rank[64];               // gt quantile queries (4 per batch)
__device__ unsigned int g_q_prefix[64];
__device__ unsigned int g_hist[64][2048];
__device__ float        g_loss[32];                 // per (batch, j) trimmed-huber loss
__device__ unsigned int g_gt_keys[(size_t)BB * N2];   // 31.5 MB
__device__ unsigned int g_rd_keys[(size_t)BB * NPIX]; // 15.7 MB
__device__ unsigned int g_ra_keys[(size_t)BB * NPIX]; // 15.7 MB

// ---------------- helpers ----------------
__device__ __forceinline__ unsigned int fkey(float x) {
    unsigned int u = __float_as_uint(x);
    return (u & 0x80000000u) ? ~u : (u | 0x80000000u);
}
__device__ __forceinline__ float kinv(unsigned int k) {
    unsigned int u = (k & 0x80000000u) ? (k & 0x7fffffffu) : ~k;
    return __uint_as_float(u);
}
__device__ __forceinline__ float hubf(float v) {
    // reference: v<=DELTA ? 0.5*v^2/DELTA : v - 0.5*DELTA, DELTA=0.03
    return (v <= 0.03f) ? (0.5f * (v * v)) / 0.03f : (v - 0.015f);
}

// 256-thread block: exclusive scan of per-thread chunk sums over sh[0..nb)
// chunk = nb/256. sP[t] = sum of sh[0 .. t*chunk), sP[256] = total.
__device__ __forceinline__ void block_exscan_chunks(const unsigned int* sh,
                                                    unsigned int* sP, int chunk) {
    int tid = threadIdx.x;
    unsigned s = 0;
#pragma unroll 4
    for (int j = 0; j < chunk; j++) s += sh[tid * chunk + j];
    int lane = tid & 31, wp = tid >> 5;
    unsigned v = s;
#pragma unroll
    for (int o = 1; o < 32; o <<= 1) {
        unsigned n = __shfl_up_sync(0xffffffffu, v, o);
        if (lane >= o) v += n;
    }
    __shared__ unsigned wtot[8];
    if (lane == 31) wtot[wp] = v;
    __syncthreads();
    unsigned wo = 0;
    for (int w = 0; w < wp; w++) wo += wtot[w];
    unsigned excl = wo + v - s;
    sP[tid] = excl;
    if (tid == 255) sP[256] = excl + s;
    __syncthreads();
}

// Single-thread: locate bin containing `rank` given scanned chunks. O(log 256 + chunk).
__device__ __forceinline__ void resolve_one(const unsigned int* sh, const unsigned int* sP,
                                            int chunk, int nb, unsigned rank,
                                            unsigned* bin_out, unsigned* rem_out) {
    int lo = 0, hi = 255;
    while (lo < hi) {
        int mid = (lo + hi + 1) >> 1;
        if (sP[mid] <= rank) lo = mid; else hi = mid - 1;
    }
    unsigned cum = sP[lo];
    int bin = lo * chunk;
    int end = bin + chunk;
    if (end > nb) end = nb;
    while (bin + 1 < end && cum + sh[bin] <= rank) { cum += sh[bin]; bin++; }
    *bin_out = (unsigned)bin;
    *rem_out = rank - cum;
}

// ---------------- kernels ----------------
__global__ void k_zero() {
    int i = blockIdx.x * blockDim.x + threadIdx.x;
    int stride = gridDim.x * blockDim.x;
    for (int x = i; x < 64 * 2048; x += stride) ((unsigned int*)g_hist)[x] = 0u;
    if (i < BB) {
        for (int j = 0; j < 5; j++) g_sums[i][j] = 0.0;
        g_cnt[i] = 0;
    }
}

// Pass 1: masked moment sums + gt key materialization + gt hist level-0 (fused)
__global__ void k_stats(const float* __restrict__ pred, const float* __restrict__ gt,
                        const float* __restrict__ mask) {
    __shared__ unsigned int hh[2048];
    int b = blockIdx.y;
    for (int i = threadIdx.x; i < 2048; i += blockDim.x) hh[i] = 0u;
    __syncthreads();
    const float4* p4 = (const float4*)(pred + (size_t)b * N2);
    const float4* g4 = (const float4*)(gt   + (size_t)b * N2);
    const float4* m4 = (const float4*)(mask + (size_t)b * N2);
    uint4* k4 = (uint4*)(g_gt_keys + (size_t)b * N2);
    float a00 = 0.f, a01 = 0.f, a11 = 0.f, bb0 = 0.f, bb1 = 0.f;
    int n4 = N2 / 4;
    for (int i = blockIdx.x * blockDim.x + threadIdx.x; i < n4; i += gridDim.x * blockDim.x) {
        float4 p = p4[i], g = g4[i], m = m4[i];
        uint4 kk;
#define DO(c) { if (m.c > 0.5f) { a00 += p.c * p.c; a01 += p.c; a11 += 1.f; \
                                  bb0 += p.c * g.c; bb1 += g.c; kk.c = fkey(g.c); } \
                else kk.c = 0xffffffffu; \
                atomicAdd(&hh[kk.c >> 21], 1u); }
        DO(x) DO(y) DO(z) DO(w)
#undef DO
        k4[i] = kk;
    }
    double d0 = a00, d1 = a01, d2 = a11, d3 = bb0, d4 = bb1;
    for (int off = 16; off > 0; off >>= 1) {
        d0 += __shfl_down_sync(0xffffffffu, d0, off);
        d1 += __shfl_down_sync(0xffffffffu, d1, off);
        d2 += __shfl_down_sync(0xffffffffu, d2, off);
        d3 += __shfl_down_sync(0xffffffffu, d3, off);
        d4 += __shfl_down_sync(0xffffffffu, d4, off);
    }
    __shared__ double sh[8][5];
    int lane = threadIdx.x & 31, w = threadIdx.x >> 5;
    if (lane == 0) { sh[w][0] = d0; sh[w][1] = d1; sh[w][2] = d2; sh[w][3] = d3; sh[w][4] = d4; }
    __syncthreads();
    if (threadIdx.x == 0) {
        double s0 = 0, s1 = 0, s2 = 0, s3 = 0, s4 = 0;
        for (int ww = 0; ww < 8; ww++) { s0 += sh[ww][0]; s1 += sh[ww][1]; s2 += sh[ww][2]; s3 += sh[ww][3]; s4 += sh[ww][4]; }
        atomicAdd(&g_sums[b][0], s0); atomicAdd(&g_sums[b][1], s1);
        atomicAdd(&g_sums[b][2], s2); atomicAdd(&g_sums[b][3], s3);
        atomicAdd(&g_sums[b][4], s4);
    }
    // flush level-0 hist (one hist per batch, index b*4)
    unsigned int* gh = g_hist[b * 4];
    for (int i = threadIdx.x; i < 2048; i += blockDim.x) {
        unsigned v = hh[i];
        if (v) atomicAdd(&gh[i], v);
    }
}

__global__ void k_solve1() {
    int b = threadIdx.x;
    if (b >= BB) return;
    double a00 = g_sums[b][0], a01 = g_sums[b][1], a11 = g_sums[b][2];
    double bb0 = g_sums[b][3], bb1 = g_sums[b][4];
    double det = a00 * a11 - a01 * a01;
    float s = 0.f, t = 0.f;
    if (det != 0.0) {
        double id = 1.0 / (det + 1e-6);
        s = (float)((a11 * bb0 - a01 * bb1) * id);
        t = (float)((-a01 * bb0 + a00 * bb1) * id);
    }
    g_sf[b] = s; g_tf[b] = t;
    int n = (int)(a11 + 0.5);
    g_nmask[b] = n;
    int nm1 = (n > 1) ? (n - 1) : 0;
    float pos05 = 0.05f * (float)nm1;
    float pos95 = 0.95f * (float)nm1;
    g_q_rank[b * 4 + 0] = (unsigned)floorf(pos05);
    g_q_rank[b * 4 + 1] = (unsigned)ceilf(pos05);
    g_q_rank[b * 4 + 2] = (unsigned)floorf(pos95);
    g_q_rank[b * 4 + 3] = (unsigned)ceilf(pos95);
    for (int j = 0; j < 4; j++) g_q_prefix[b * 4 + j] = 0u;
}

// Parallel resolve: level 0 -> 16 blocks (4 queries share hist b*4);
// level 1/2 -> 64 blocks (one per query). Zeroes its hist afterward.
__global__ void k_resolve_gt(int level) {
    __shared__ unsigned int sh[2048];
    __shared__ unsigned int sP[257];
    int tid = threadIdx.x;
    int nb = (level == 2) ? 1024 : 2048;
    int chunk = nb / 256;
    int hq, qbase, nq;
    if (level == 0) { hq = blockIdx.x * 4; qbase = hq; nq = 4; }
    else            { hq = blockIdx.x;     qbase = hq; nq = 1; }
    unsigned int* hist = g_hist[hq];
    for (int i = tid; i < nb; i += 256) sh[i] = hist[i];
    __syncthreads();
    block_exscan_chunks(sh, sP, chunk);
    if (tid < nq) {
        int q = qbase + tid;
        unsigned bin, rem;
        resolve_one(sh, sP, chunk, nb, g_q_rank[q], &bin, &rem);
        g_q_rank[q] = rem;
        g_q_prefix[q] = g_q_prefix[q] * (unsigned)nb + bin;
    }
    __syncthreads();
    for (int i = tid; i < 2048; i += 256) hist[i] = 0u;   // ready for next level / replay
}

__global__ void k_hist_gt(int level) {  // level 1 or 2
    __shared__ unsigned int h[4][2048];
    int b = blockIdx.y;
    for (int i = threadIdx.x; i < 4 * 2048; i += blockDim.x) ((unsigned int*)h)[i] = 0u;
    __syncthreads();
    unsigned pref0 = g_q_prefix[b * 4 + 0], pref1 = g_q_prefix[b * 4 + 1];
    unsigned pref2 = g_q_prefix[b * 4 + 2], pref3 = g_q_prefix[b * 4 + 3];
    int hishift = (level == 1) ? 21 : 10;
    int shift   = (level == 1) ? 10 : 0;
    unsigned bmask = (level == 1) ? 2047u : 1023u;
    const uint4* k4 = (const uint4*)(g_gt_keys + (size_t)b * N2);
    int n4 = N2 / 4;
    for (int i = blockIdx.x * blockDim.x + threadIdx.x; i < n4; i += gridDim.x * blockDim.x) {
        uint4 kk = k4[i];
        unsigned a[4] = {kk.x, kk.y, kk.z, kk.w};
#pragma unroll
        for (int e = 0; e < 4; e++) {
            unsigned key = a[e];
            unsigned hi = key >> hishift;
            unsigned bin = (key >> shift) & bmask;
            if (hi == pref0) atomicAdd(&h[0][bin], 1u);
            if (hi == pref1) atomicAdd(&h[1][bin], 1u);
            if (hi == pref2) atomicAdd(&h[2][bin], 1u);
            if (hi == pref3) atomicAdd(&h[3][bin], 1u);
        }
    }
    __syncthreads();
    for (int j = 0; j < 4; j++)
        for (int i = threadIdx.x; i < 2048; i += blockDim.x) {
            unsigned v = h[j][i];
            if (v) atomicAdd(&g_hist[b * 4 + j][i], v);
        }
}

__global__ void k_rr() {
    int b = threadIdx.x;
    if (b >= BB) return;
    int n = g_nmask[b];
    float rr = 1.0f;
    if (n > 0) {
        float v0 = kinv(g_q_prefix[b * 4 + 0]);
        float v1 = kinv(g_q_prefix[b * 4 + 1]);
        float v2 = kinv(g_q_prefix[b * 4 + 2]);
        float v3 = kinv(g_q_prefix[b * 4 + 3]);
        int nm1 = (n > 1) ? (n - 1) : 0;
        float pos05 = 0.05f * (float)nm1, pos95 = 0.95f * (float)nm1;
        float lo = v0 + (v1 - v0) * (pos05 - floorf(pos05));
        float hi = v2 + (v3 - v2) * (pos95 - floorf(pos95));
        bool valid = isfinite(lo) && isfinite(hi) && (hi - lo > 0.f) &&
                     (fabsf(lo) < 1e30f) && (fabsf(hi) < 1e30f);
        rr = valid ? fmaxf(hi - lo, 1e-6f) : 1.0f;
    }
    g_rr[b] = rr;
    g_scale[b] = fmaxf(rr, 1e-6f);
    g_th[b] = 0.01f * rr;
}

// curr_grad output + compaction of static residual keys
__global__ void k_compact(const float* __restrict__ pred, const float* __restrict__ gt,
                          const float* __restrict__ mask, const float* __restrict__ prev,
                          float* __restrict__ out) {
    int b = blockIdx.y;
    float s = g_sf[b], t = g_tf[b], th = g_th[b], sc = g_scale[b];
    const float4* p0 = (const float4*)(pred + (size_t)b * N2);
    const float4* p1 = (const float4*)(pred + (size_t)b * N2 + NPIX);
    const float4* g0 = (const float4*)(gt   + (size_t)b * N2);
    const float4* g1 = (const float4*)(gt   + (size_t)b * N2 + NPIX);
    const float4* m0 = (const float4*)(mask + (size_t)b * N2);
    const float4* m1 = (const float4*)(mask + (size_t)b * N2 + NPIX);
    const float4* pv = (const float4*)(prev + (size_t)b * NPIX);
    float4* o4 = (float4*)(out + 4 + (size_t)b * NPIX);
    int n4 = NPIX / 4;
    for (int i = blockIdx.x * blockDim.x + threadIdx.x; i < n4; i += gridDim.x * blockDim.x) {
        float4 P0 = p0[i], P1 = p1[i], G0 = g0[i], G1 = g1[i], M0 = m0[i], M1 = m1[i], PV = pv[i];
        float4 DP;
#define DO(c) { float A0 = fmaf(s, P0.c, t); float A1 = fmaf(s, P1.c, t); \
                float dp = A1 - A0; DP.c = dp; \
                float dg = G1.c - G0.c; \
                if (M0.c > 0.5f && M1.c > 0.5f && fabsf(dg) < th) { \
                    int pos = atomicAdd(&g_cnt[b], 1); \
                    g_rd_keys[(size_t)b * NPIX + pos] = fkey(fabsf(dp - dg) / sc); \
                    g_ra_keys[(size_t)b * NPIX + pos] = fkey(fabsf(dp - PV.c) / sc); } }
        DO(x) DO(y) DO(z) DO(w)
#undef DO
        o4[i] = DP;
    }
}

// Full trimmed-huber: per (batch, j) block does 3-level shared-mem radix select
// over compacted keys, then huber sum with tie-correct threshold handling.
__global__ void k_trim() {
    __shared__ unsigned int sh[2048];
    __shared__ unsigned int sP[257];
    __shared__ unsigned int s_prefix, s_rank;
    int tid = threadIdx.x;
    int b = blockIdx.y, j = blockIdx.x;
    const unsigned int* keys = (j ? g_ra_keys : g_rd_keys) + (size_t)b * NPIX;
    int cnt = g_cnt[b];
    int k = (int)floorf(0.6f * (float)cnt);   // (1.0-TRIM) in f32, mirrors reference
    if (k <= 0) { if (tid == 0) g_loss[b * 2 + j] = 0.f; return; }
    if (tid == 0) { s_rank = (unsigned)(k - 1); s_prefix = 0u; }
    __syncthreads();
    for (int level = 0; level < 3; level++) {
        int nb = (level == 2) ? 1024 : 2048;
        for (int i = tid; i < nb; i += 256) sh[i] = 0u;
        __syncthreads();
        unsigned pref = s_prefix;
        for (int i = tid; i < cnt; i += 256) {
            unsigned key = keys[i];
            if (level == 0) atomicAdd(&sh[key >> 21], 1u);
            else if (level == 1) { if ((key >> 21) == pref) atomicAdd(&sh[(key >> 10) & 2047u], 1u); }
            else                 { if ((key >> 10) == pref) atomicAdd(&sh[key & 1023u], 1u); }
        }
        __syncthreads();
        block_exscan_chunks(sh, sP, nb / 256);
        if (tid == 0) {
            unsigned bin, rem;
            resolve_one(sh, sP, nb / 256, nb, s_rank, &bin, &rem);
            s_rank = rem;
            s_prefix = pref * (unsigned)nb + bin;
        }
        __syncthreads();
    }
    unsigned target = s_prefix;   // key of k-th smallest residual
    float sum = 0.f;
    unsigned less = 0;
    for (int i = tid; i < cnt; i += 256) {
        unsigned key = keys[i];
        if (key < target) { sum += hubf(kinv(key)); less++; }
    }
    for (int o = 16; o > 0; o >>= 1) {
        sum  += __shfl_down_sync(0xffffffffu, sum, o);
        less += __shfl_down_sync(0xffffffffu, less, o);
    }
    __shared__ float ss[8];
    __shared__ unsigned sl[8];
    int lane = tid & 31, wp = tid >> 5;
    if (lane == 0) { ss[wp] = sum; sl[wp] = less; }
    __syncthreads();
    if (tid == 0) {
        float S = 0.f; unsigned L = 0;
        for (int w = 0; w < 8; w++) { S += ss[w]; L += sl[w]; }
        float ht = hubf(kinv(target));
        g_loss[b * 2 + j] = (S + (float)(k - (int)L) * ht) / (float)k;
    }
}

__global__ void k_final(float* __restrict__ out) {
    __shared__ float ld[BB], la[BB], rs[BB];
    int b = threadIdx.x;
    if (b < BB) { ld[b] = g_loss[b * 2]; la[b] = g_loss[b * 2 + 1]; rs[b] = g_rr[b]; }
    __syncthreads();
    if (threadIdx.x == 0) {
        float sld = 0.f, sla = 0.f, srr = 0.f;
        for (int i = 0; i < BB; i++) { sld += ld[i]; sla += la[i]; srr += rs[i]; }
        float loss_data = sld / (float)BB;
        float loss_acc  = sla / (float)BB;
        out[0] = loss_data + 0.2f * loss_acc;
        out[1] = loss_data;
        out[2] = loss_acc;
        out[3] = srr / (float)BB;
    }
}

extern "C" void kernel_launch(void* const* d_in, const int* in_sizes, int n_in,
                              void* d_out, int out_size) {
    const float* pred = (const float*)d_in[0];
    const float* gt   = (const float*)d_in[1];
    const float* mask = (const float*)d_in[2];
    const float* prev = (const float*)d_in[3];
    float* out = (float*)d_out;
    dim3 big(60, BB);

    k_zero<<<64, 256>>>();
    k_stats<<<big, 256>>>(pred, gt, mask);          // moments + keys + hist L0
    k_solve1<<<1, 32>>>();
    k_resolve_gt<<<16, 256>>>(0);
    k_hist_gt<<<big, 256>>>(1);
    k_resolve_gt<<<64, 256>>>(1);
    k_hist_gt<<<big, 256>>>(2);
    k_resolve_gt<<<64, 256>>>(2);
    k_rr<<<1, 16>>>();
    k_compact<<<big, 256>>>(pred, gt, mask, prev, out);
    k_trim<<<dim3(2, BB), 256>>>();
    k_final<<<1, 32>>>(out);
}